// round 16
// baseline (speedup 1.0000x reference)
#include <cuda_runtime.h>
#include <cuda_bf16.h>
#include <cuda_fp16.h>
#include <math.h>
#include <stdint.h>
#include <string.h>

#define NB 16
#define NC 64
#define NT 128
#define ND 256
#define NH 8
#define NKD 32
#define NTOPK 8

// ======================= helpers =======================
__device__ __forceinline__ uint32_t smem_to_u32(const void* p) {
    uint32_t a;
    asm("{ .reg .u64 t; cvta.to.shared.u64 t, %1; cvt.u32.u64 %0, t; }" : "=r"(a) : "l"(p));
    return a;
}
#define CP_ASYNC16(sa, gp) \
    asm volatile("cp.async.cg.shared.global [%0], [%1], 16;" :: "r"(sa), "l"(gp))
#define CP_COMMIT() asm volatile("cp.async.commit_group;")
#define CP_WAIT0()  asm volatile("cp.async.wait_group 0;")
#define CP_WAIT1()  asm volatile("cp.async.wait_group 1;")

__device__ __forceinline__ void ldsm_x4(uint32_t* r, uint32_t addr) {
    asm volatile("ldmatrix.sync.aligned.m8n8.x4.shared.b16 {%0,%1,%2,%3}, [%4];"
                 : "=r"(r[0]), "=r"(r[1]), "=r"(r[2]), "=r"(r[3]) : "r"(addr));
}
__device__ __forceinline__ void ldsm_x4_t(uint32_t* r, uint32_t addr) {
    asm volatile("ldmatrix.sync.aligned.m8n8.x4.trans.shared.b16 {%0,%1,%2,%3}, [%4];"
                 : "=r"(r[0]), "=r"(r[1]), "=r"(r[2]), "=r"(r[3]) : "r"(addr));
}
__device__ __forceinline__ void mma16816f16(float* d, const uint32_t* a, const uint32_t* b) {
    asm volatile(
        "mma.sync.aligned.m16n8k16.row.col.f32.f16.f16.f32 "
        "{%0,%1,%2,%3}, {%4,%5,%6,%7}, {%8,%9}, {%0,%1,%2,%3};"
        : "+f"(d[0]), "+f"(d[1]), "+f"(d[2]), "+f"(d[3])
        : "r"(a[0]), "r"(a[1]), "r"(a[2]), "r"(a[3]), "r"(b[0]), "r"(b[1]));
}
__device__ __forceinline__ uint16_t f16_bits(float v) {
    __half h = __float2half_rn(v);
    uint16_t b; memcpy(&b, &h, 2);
    return b;
}

// ======================= device scratch =======================
__device__ float g_q[NB * NC * NKD];
__device__ float g_k[NB * NC * NKD];
__device__ unsigned long long g_maskcol[NB * NC];
__device__ float g_vsrc[NH * ND];
__device__ float g_vdst[NH * ND];
__device__ uint16_t g_gf16[NH * ND * ND];   // G as f16 [2048 rows][256 k]
__device__ unsigned int g_tilectr;

// ======================= kernel: fused v_src/v_dst + G->f16 (+counter reset) =======================
__global__ void k_prep(const float* __restrict__ gat_lin,
                       const float* __restrict__ att_src,
                       const float* __restrict__ att_dst) {
    int bx = blockIdx.x;
    int tid = threadIdx.x;
    if (bx < 16) {
        int h = bx & 7;
        int isdst = bx >> 3;
        const float* att = isdst ? att_dst : att_src;
        float acc = 0.f;
#pragma unroll 4
        for (int f = 0; f < ND; ++f)
            acc += att[h * ND + f] * gat_lin[((size_t)(h * ND + f)) * ND + tid];
        (isdst ? g_vdst : g_vsrc)[h * ND + tid] = acc;
    } else {
        if (bx == 16 && tid == 0) g_tilectr = 0;
        uint32_t i = (uint32_t)(bx - 16) * 256 + tid;
        g_gf16[i] = f16_bits(gat_lin[i]);
    }
}

// ======================= kernel: fused temporal mean + q/k projections =======================
__global__ __launch_bounds__(256)
void k_hqk(const float* __restrict__ x,
           const float* __restrict__ w_q, const float* __restrict__ w_k) {
    __shared__ float hs[8 * ND];
    int blk = blockIdx.x;               // 128 blocks x 8 bc rows
    int tid = threadIdx.x;
    // temporal mean for 8 (b,c) rows, thread = d
#pragma unroll
    for (int r = 0; r < 8; ++r) {
        size_t bc = (size_t)blk * 8 + r;
        const float* p = x + bc * NT * ND + tid;
        float s = 0.f;
#pragma unroll 8
        for (int t = 0; t < NT; ++t) s += p[(size_t)t * ND];
        hs[r * ND + tid] = s * (1.0f / NT);
    }
    if (tid < 8) g_maskcol[blk * 8 + tid] = 1ull << ((blk * 8 + tid) & 63);
    __syncthreads();
#pragma unroll
    for (int k = 0; k < 2; ++k) {
        int o = tid + k * 256;
        int bcL = o >> 6, rem = o & 63;
        int which = rem >> 5, kd = rem & 31;
        const float4* w4 = (const float4*)((which ? w_k : w_q) + (size_t)kd * ND);
        const float* hr = hs + bcL * ND;
        float acc = 0.f;
#pragma unroll 8
        for (int d4 = 0; d4 < 64; ++d4) {
            float4 wv = __ldg(w4 + d4);
            acc += hr[d4 * 4] * wv.x + hr[d4 * 4 + 1] * wv.y
                 + hr[d4 * 4 + 2] * wv.z + hr[d4 * 4 + 3] * wv.w;
        }
        (which ? g_k : g_q)[(blk * 8 + bcL) * NKD + kd] = acc;
    }
}

// ======================= kernel: sim + tanh + top-k (merged) =======================
__global__ __launch_bounds__(256)
void k_simtopk(const float* __restrict__ static_adj, float* __restrict__ delta_out) {
    __shared__ float qs[16 * NKD];
    __shared__ float ks_[NC * NKD];
    __shared__ float arow[16 * NC];
    int b = blockIdx.x >> 2;
    int i0 = (blockIdx.x & 3) * 16;
    int tid = threadIdx.x;
    for (int it = tid; it < NC * NKD; it += 256) ks_[it] = g_k[b * NC * NKD + it];
    for (int it = tid; it < 16 * NKD; it += 256) qs[it] = g_q[b * NC * NKD + i0 * NKD + it];
    __syncthreads();
    const float inv = 0.17677669529663687f;
    for (int task = tid; task < 16 * NC; task += 256) {
        int i = task >> 6, j = task & 63;
        float acc = 0.f;
#pragma unroll
        for (int kd = 0; kd < NKD; ++kd) acc += qs[i * NKD + kd] * ks_[j * NKD + kd];
        float delta = tanhf(acc * inv);
        int gi = i0 + i;
        delta_out[b * NC * NC + gi * NC + j] = delta;
        arow[task] = static_adj[gi * NC + j] + delta;
    }
    __syncthreads();
    int w = tid >> 5, lane = tid & 31;
#pragma unroll
    for (int rr = 0; rr < 2; ++rr) {
        int i = w * 2 + rr;
        int gi = i0 + i;
        float v0 = fabsf(arow[i * NC + lane]);
        float v1 = fabsf(arow[i * NC + lane + 32]);
        for (int s = 0; s < NTOPK; ++s) {
            float bv; int bj;
            if (v0 >= v1) { bv = v0; bj = lane; } else { bv = v1; bj = lane + 32; }
#pragma unroll
            for (int off = 16; off > 0; off >>= 1) {
                float ov = __shfl_xor_sync(0xffffffffu, bv, off);
                int   oj = __shfl_xor_sync(0xffffffffu, bj, off);
                if (ov > bv || (ov == bv && oj < bj)) { bv = ov; bj = oj; }
            }
            if (lane == 0) atomicOr(&g_maskcol[b * NC + bj], 1ull << gi);
            if (bj == lane)      v0 = -1.0f;
            if (bj == lane + 32) v1 = -1.0f;
        }
    }
}

// ======================= PERSISTENT fused kernel (pipelined agg + shadowed softmax) =======================
#define MTHREADS 512
#define SM_A 0                        // 32768: A f16 [chunk4][64r][128B]
#define SM_B 32768                    // 65536: 2 stages x [kh2][128r][128B]
#define SM_WX 98304                   // 32768: 2 x 16384 wx f16 buffers
#define SM_ALPHA 131072               // 18432: 2 x 9216 f16 alpha [64][72] (vt overlay)
#define SM_ASAD 149504                // 4096
#define SM_XSTG 153600                // 65536
#define SM_IDS 219136                 // 16
#define SM_MAIN 219152
#define NTILES 2048

__device__ __forceinline__ void process_x(char* smem, int tid) {
    const float* stgf = (const float*)(smem + SM_XSTG);
    const float* vt = (const float*)(smem + SM_ALPHA);
    float* as_s = (float*)(smem + SM_ASAD);
    float* ad_s = as_s + 512;
#pragma unroll
    for (int k = 0; k < 2; ++k) {
        int task = tid + k * MTHREADS;
        int c = task >> 4, hv = task & 15, h = hv & 7, sd = hv >> 3;
        const float* sr = stgf + c * 256;
        const float* vr = vt + hv;
        float acc = 0.f;
#pragma unroll 8
        for (int d = 0; d < 256; ++d) acc += sr[d] * vr[d * 17];
        (sd ? ad_s : as_s)[h * 64 + c] = acc;
    }
#pragma unroll
    for (int k = 0; k < 4; ++k) {
        int it = tid + k * MTHREADS;
        int c = it >> 5, c64 = (it >> 3) & 3, gn = it & 7;
        const float* src = stgf + c * 256 + c64 * 64 + gn * 8;
        uint32_t wv[4];
#pragma unroll
        for (int p = 0; p < 4; ++p)
            wv[p] = (uint32_t)f16_bits(src[2 * p]) | ((uint32_t)f16_bits(src[2 * p + 1]) << 16);
        uint32_t off = (uint32_t)(c * 128 + ((gn * 16) ^ ((c & 7) << 4)));
        *(uint4*)(smem + SM_A + c64 * 8192 + off) = make_uint4(wv[0], wv[1], wv[2], wv[3]);
    }
}

__device__ __forceinline__ void load_vt(char* smem, int tid) {
    float* vt = (float*)(smem + SM_ALPHA);
    for (int it = tid; it < 2048; it += MTHREADS) {
        int h = it >> 8, d = it & 255;
        vt[d * 17 + h]     = g_vsrc[it];
        vt[d * 17 + 8 + h] = g_vdst[it];
    }
}

__global__ __launch_bounds__(MTHREADS, 1)
void k_main(const float* __restrict__ x,
            const float* __restrict__ gat_bias,
            float* __restrict__ out) {
    extern __shared__ char smem[];
    uint32_t sb = smem_to_u32(smem);
    const int tid = threadIdx.x;
    const int w = tid >> 5, l = tid & 31;
    unsigned int* ids = (unsigned int*)(smem + SM_IDS);

    const char* gp = (const char*)g_gf16;

    // ---------------- prologue ----------------
    if (tid == 0) ids[0] = atomicAdd(&g_tilectr, 1u);
    __syncthreads();
    unsigned int id = ids[0];
    if (id >= NTILES) return;
    int b = id >> 7, t = id & 127;

#pragma unroll
    for (int ii = 0; ii < 8; ++ii) {
        int it = tid + ii * MTHREADS;
        int c = it >> 6, q = it & 63;
        CP_ASYNC16(sb + SM_XSTG + (uint32_t)(c * 1024 + q * 16),
                   x + (((size_t)(b * 64 + c) * 128) + t) * 256 + q * 4);
    }
    CP_COMMIT();
#pragma unroll
    for (int ii = 0; ii < 4; ++ii) {
        int it = tid + ii * MTHREADS;
        int kh = it >> 10, r = (it >> 3) & 127, q = it & 7;
        CP_ASYNC16(sb + SM_B + (uint32_t)(kh * 16384 + r * 128 + ((q * 16) ^ ((r & 7) << 4))),
                   gp + ((size_t)r * 512 + kh * 128 + q * 16));
    }
    CP_COMMIT();
    load_vt(smem, tid);
    CP_WAIT1();          // X landed
    __syncthreads();
    process_x(smem, tid);
    if (tid == 0) ids[1] = atomicAdd(&g_tilectr, 1u);

    // ---------------- frag geometry ----------------
    const int mw2 = w & 3, nw2 = w >> 2;
    const int arow_g = mw2 * 16 + (l & 15);
    const uint32_t aoff = (uint32_t)(arow_g * 128);
    const uint32_t akx = (uint32_t)((arow_g & 7) << 4);
    const uint32_t akoff = (uint32_t)((l >> 4) * 16);
    int boff[2]; uint32_t bkx[2];
#pragma unroll
    for (int p = 0; p < 2; ++p) {
        int r = nw2 * 32 + p * 16 + (l & 7) + (l >> 4) * 8;
        boff[p] = r * 128;
        bkx[p] = (uint32_t)((r & 7) << 4);
    }
    const uint32_t bkoff = (uint32_t)(((l >> 3) & 1) * 16);
    const uint32_t aoffA = (uint32_t)(((mw2 * 16 + (l & 15)) * 72 + (l >> 4) * 8) * 2);
    const int aggI = (l & 7) + ((l >> 3) & 1) * 8;
    const int aggF = nw2 * 32 + (l >> 4) * 8;

    float* as_s = (float*)(smem + SM_ASAD);
    float* ad_s = as_s + 512;

    unsigned long long msk[4];
#pragma unroll
    for (int jj = 0; jj < 4; ++jj) msk[jj] = g_maskcol[b * NC + w * 4 + jj];

    float wx_acc[4][4];
#pragma unroll
    for (int g = 0; g < 4; ++g)
#pragma unroll
        for (int q = 0; q < 4; ++q) wx_acc[g][q] = 0.f;
    float out_acc[2][4][4];
#pragma unroll
    for (int hh = 0; hh < 2; ++hh)
#pragma unroll
        for (int g = 0; g < 4; ++g)
#pragma unroll
            for (int q = 0; q < 4; ++q) out_acc[hh][g][q] = 0.f;

    const float NEGINF = __int_as_float(0xff800000);
    int buf = 0;
    unsigned int nextid = NTILES;

#define DO_AGG(prev_nt) do { \
        const int _p = (prev_nt); \
        const uint32_t _wb = sb + SM_WX + (uint32_t)((_p & 1) * 16384); \
        const uint32_t _ab = sb + SM_ALPHA + (uint32_t)(((_p >> 1) & 1) * 9216); \
        const int _hh = _p & 1; \
        _Pragma("unroll") \
        for (int ks = 0; ks < 4; ++ks) { \
            uint32_t aah[4], wbh[2][4]; \
            ldsm_x4(aah, _ab + aoffA + (uint32_t)(ks * 32)); \
            _Pragma("unroll") \
            for (int n2 = 0; n2 < 2; ++n2) { \
                int i = ks * 16 + aggI; \
                int f = aggF + n2 * 16; \
                uint32_t off = (uint32_t)((i * 2 + (f >> 6)) * 128 + (((f & 63) * 2) ^ ((i & 7) << 4))); \
                ldsm_x4_t(wbh[n2], _wb + off); \
            } \
            _Pragma("unroll") \
            for (int q = 0; q < 4; ++q) { \
                const int n2 = q >> 1, o = (q & 1) * 2; \
                mma16816f16(out_acc[_hh][q], aah, &wbh[n2][o]); \
            } \
        } \
    } while (0)

    // ---------------- persistent tile loop ----------------
    for (;;) {
        for (int s = 0; s < 32; ++s) {
            const int nt = s >> 1, kb2 = s & 1;
            __syncthreads();
            if (s == 0) nextid = ids[1];

            // issue B(s+1) (+X prefetch for s<8)
            {
                int ss2 = (s + 1) & 31;
                int nn = ss2 >> 1, nk = ss2 & 1;
                int b2 = buf ^ 1;
#pragma unroll
                for (int ii = 0; ii < 4; ++ii) {
                    int it = tid + ii * MTHREADS;
                    int kh = it >> 10, r = (it >> 3) & 127, q = it & 7;
                    CP_ASYNC16(sb + SM_B + (uint32_t)(b2 * 32768 + kh * 16384 + r * 128 + ((q * 16) ^ ((r & 7) << 4))),
                               gp + ((size_t)(nn * 128 + r) * 512 + nk * 256 + kh * 128 + q * 16));
                }
                if (s < 8 && nextid < NTILES) {
                    int it = tid + s * MTHREADS;
                    int c = it >> 6, q = it & 63;
                    int nb = nextid >> 7, ntt = nextid & 127;
                    CP_ASYNC16(sb + SM_XSTG + (uint32_t)(c * 1024 + q * 16),
                               x + (((size_t)(nb * 64 + c) * 128) + ntt) * 256 + q * 4);
                }
                CP_COMMIT();
            }

            // B-landing shadow: agg(nt-1) on kb2==1, softmax on head-start kb2==0
            if (kb2 == 1) {
                if (nt > 0) DO_AGG(nt - 1);
            } else if ((nt & 1) == 0) {
                int h = nt >> 1;
                uint16_t* alw = (uint16_t*)(smem + SM_ALPHA + (h & 1) * 9216);
#pragma unroll
                for (int jj = 0; jj < 4; ++jj) {
                    int j = w * 4 + jj;
                    unsigned long long m = msk[jj];
                    float adj = ad_s[h * 64 + j];
                    int i0 = l, i1 = l + 32;
                    float e0 = as_s[h * 64 + i0] + adj;
                    float e1 = as_s[h * 64 + i1] + adj;
                    e0 = e0 > 0.f ? e0 : 0.2f * e0;
                    e1 = e1 > 0.f ? e1 : 0.2f * e1;
                    bool m0 = (m >> i0) & 1ull;
                    bool m1 = (m >> i1) & 1ull;
                    float mx = fmaxf(m0 ? e0 : NEGINF, m1 ? e1 : NEGINF);
#pragma unroll
                    for (int off = 16; off > 0; off >>= 1)
                        mx = fmaxf(mx, __shfl_xor_sync(0xffffffffu, mx, off));
                    float p0 = m0 ? expf(e0 - mx) : 0.f;
                    float p1 = m1 ? expf(e1 - mx) : 0.f;
                    float ssum = p0 + p1;
#pragma unroll
                    for (int off = 16; off > 0; off >>= 1)
                        ssum += __shfl_xor_sync(0xffffffffu, ssum, off);
                    float invs = 1.0f / ssum;
                    alw[j * 72 + i0] = f16_bits(p0 * invs);
                    alw[j * 72 + i1] = f16_bits(p1 * invs);
                }
            }

            CP_WAIT1();

            // f16 HMMA gemm
#pragma unroll
            for (int kh = 0; kh < 2; ++kh) {
                const uint32_t pA = sb + SM_A + (uint32_t)((kb2 * 2 + kh) * 8192);
                const uint32_t pB = sb + SM_B + (uint32_t)(buf * 32768 + kh * 16384);
#pragma unroll
                for (int ks = 0; ks < 4; ++ks) {
                    uint32_t ah[4], bh[2][4];
                    uint32_t akb = ((uint32_t)(ks * 32) + akoff) ^ akx;
                    ldsm_x4(ah, pA + aoff + akb);
#pragma unroll
                    for (int p = 0; p < 2; ++p) {
                        uint32_t kbyte = ((uint32_t)(ks * 32) + bkoff) ^ bkx[p];
                        ldsm_x4(bh[p], pB + boff[p] + kbyte);
                    }
#pragma unroll
                    for (int g = 0; g < 4; ++g) {
                        const int p = g >> 1, o = (g & 1) * 2;
                        mma16816f16(wx_acc[g], ah, &bh[p][o]);
                    }
                }
            }

            if (kb2 == 1) {
                // store wx tile into WX[nt&1]
                char* wxb = smem + SM_WX + (nt & 1) * 16384;
                int r1 = mw2 * 16 + (l >> 2);
#pragma unroll
                for (int g = 0; g < 4; ++g) {
                    int f = nw2 * 32 + g * 8 + (l & 3) * 2;
                    int fh = f >> 6, fb = (f & 63) * 2;
#pragma unroll
                    for (int half = 0; half < 2; ++half) {
                        int r = r1 + half * 8;
                        uint16_t h0 = f16_bits(wx_acc[g][half * 2]);
                        uint16_t h1 = f16_bits(wx_acc[g][half * 2 + 1]);
                        uint32_t off = (uint32_t)((r * 2 + fh) * 128 + (fb ^ ((r & 7) << 4)));
                        *(uint32_t*)(wxb + off) = (uint32_t)h0 | ((uint32_t)h1 << 16);
                    }
                    wx_acc[g][0] = wx_acc[g][1] = wx_acc[g][2] = wx_acc[g][3] = 0.f;
                }
            }
            buf ^= 1;
        }

        // ---------------- tile boundary ----------------
        __syncthreads();        // order WX[1] stores before final agg
        DO_AGG(15);
        {
            const float inv8 = 0.125f;
            int j0 = mw2 * 16 + (l >> 2);
#pragma unroll
            for (int hh = 0; hh < 2; ++hh) {
#pragma unroll
                for (int q = 0; q < 4; ++q) {
                    int f = hh * 128 + nw2 * 32 + q * 8 + (l & 3) * 2;
                    float b0 = __ldg(gat_bias + f), b1 = __ldg(gat_bias + f + 1);
                    float2 v0 = make_float2(out_acc[hh][q][0] * inv8 + b0, out_acc[hh][q][1] * inv8 + b1);
                    float2 v1 = make_float2(out_acc[hh][q][2] * inv8 + b0, out_acc[hh][q][3] * inv8 + b1);
                    *(float2*)(out + (((size_t)b * NC + j0) * NT + t) * ND + f) = v0;
                    *(float2*)(out + (((size_t)b * NC + j0 + 8) * NT + t) * ND + f) = v1;
                    out_acc[hh][q][0] = out_acc[hh][q][1] = out_acc[hh][q][2] = out_acc[hh][q][3] = 0.f;
                }
            }
        }
        unsigned int nid = nextid;
        __syncthreads();        // all agg reads of ALPHA done before vt overlay
        if (nid >= NTILES) { CP_WAIT0(); break; }
        id = nid; b = id >> 7; t = id & 127;
        load_vt(smem, tid);
        if (tid == 0) ids[1] = atomicAdd(&g_tilectr, 1u);
        __syncthreads();        // vt visible before process_x
        process_x(smem, tid);
#pragma unroll
        for (int jj = 0; jj < 4; ++jj) msk[jj] = g_maskcol[b * NC + w * 4 + jj];
    }
#undef DO_AGG
}

// ======================= launch =======================
extern "C" void kernel_launch(void* const* d_in, const int* in_sizes, int n_in,
                              void* d_out, int out_size) {
    const float* x          = (const float*)d_in[0];
    const float* static_adj = (const float*)d_in[1];
    const float* w_q        = (const float*)d_in[2];
    const float* w_k        = (const float*)d_in[3];
    const float* gat_lin    = (const float*)d_in[4];
    const float* att_src    = (const float*)d_in[5];
    const float* att_dst    = (const float*)d_in[6];
    const float* gat_bias   = (const float*)d_in[7];

    float* out = (float*)d_out;
    float* delta_out = out + (size_t)NB * NC * NT * ND;

    int nsm = 148;
    cudaDeviceGetAttribute(&nsm, cudaDevAttrMultiProcessorCount, 0);
    if (nsm <= 0) nsm = 148;
    if (nsm > NTILES) nsm = NTILES;

    cudaFuncSetAttribute(k_main, cudaFuncAttributeMaxDynamicSharedMemorySize, SM_MAIN);

    k_prep<<<16 + 2048, 256>>>(gat_lin, att_src, att_dst);
    k_hqk<<<NB * NC / 8, 256>>>(x, w_q, w_k);
    k_simtopk<<<NB * 4, 256>>>(static_adj, delta_out);
    k_main<<<nsm, MTHREADS, SM_MAIN>>>(x, gat_bias, out);
}